// round 14
// baseline (speedup 1.0000x reference)
#include <cuda_runtime.h>
#include <cuda_fp16.h>
#include <cstdint>

#define N_NODES 50000
#define N_EDGES 800000
#define D 512
#define M_PAD 50048            // 391 * 128

// ---------------------------------------------------------------------------
// Device scratch
// ---------------------------------------------------------------------------
__device__ __half g_h[(size_t)M_PAD * D];                // GEMM output fp16 (51.2 MB)
__device__ __half g_Af[(size_t)M_PAD * D];               // A in fp16 (51.2 MB)
__device__ __half g_Btf[(size_t)D * D];                  // weight^T fp16 [n][k]
__device__ int g_rowptr[N_NODES + 1];

// ---------------------------------------------------------------------------
// helpers
// ---------------------------------------------------------------------------
__device__ __forceinline__ uint32_t smem_to_u32(const void* p) {
    uint32_t a;
    asm("{ .reg .u64 t; cvta.to.shared.u64 t, %1; cvt.u32.u64 %0, t; }" : "=r"(a) : "l"(p));
    return a;
}
__device__ __forceinline__ uint32_t swz128(uint32_t o) { return o ^ ((o >> 3) & 0x70); }

__device__ __forceinline__ void cp_async16(uint32_t saddr, const void* gptr) {
    asm volatile("cp.async.cg.shared.global [%0], [%1], 16;" :: "r"(saddr), "l"(gptr));
}
#define CP_COMMIT() asm volatile("cp.async.commit_group;" ::: "memory")
#define CP_WAIT(n) asm volatile("cp.async.wait_group %0;" :: "n"(n) : "memory")

__device__ __forceinline__ void ldsm4(uint32_t r[4], uint32_t addr) {
    asm volatile("ldmatrix.sync.aligned.m8n8.x4.shared.b16 {%0,%1,%2,%3}, [%4];"
                 : "=r"(r[0]), "=r"(r[1]), "=r"(r[2]), "=r"(r[3]) : "r"(addr));
}
__device__ __forceinline__ void mma16816h(float c[4], const uint32_t a[4], const uint32_t b[2]) {
    asm volatile("mma.sync.aligned.m16n8k16.row.col.f32.f16.f16.f32 "
                 "{%0,%1,%2,%3}, {%4,%5,%6,%7}, {%8,%9}, {%0,%1,%2,%3};"
                 : "+f"(c[0]), "+f"(c[1]), "+f"(c[2]), "+f"(c[3])
                 : "r"(a[0]), "r"(a[1]), "r"(a[2]), "r"(a[3]), "r"(b[0]), "r"(b[1]));
}

// ---------------------------------------------------------------------------
// Convert kernels (fp32 -> fp16)
// ---------------------------------------------------------------------------
__global__ __launch_bounds__(256) void convertA_kernel(const float* __restrict__ A,
                                                       __half* __restrict__ Af) {
    const size_t i4 = (size_t)blockIdx.x * blockDim.x + threadIdx.x;
    const size_t total4 = (size_t)M_PAD * D / 4;
    if (i4 >= total4) return;
    const size_t elem = i4 * 4;
    const size_t row = elem >> 9;
    float4 v = make_float4(0.f, 0.f, 0.f, 0.f);
    if (row < N_NODES) v = *reinterpret_cast<const float4*>(A + elem);
    __half2* p = reinterpret_cast<__half2*>(Af + elem);
    p[0] = __floats2half2_rn(v.x, v.y);
    p[1] = __floats2half2_rn(v.z, v.w);
}

// weight [k][n] row-major -> Bt[n][k] fp16
__global__ void convertW_kernel(const float* __restrict__ W, __half* __restrict__ Bt) {
    __shared__ float tile[32][33];
    const int k = blockIdx.y * 32 + threadIdx.y;
    const int n = blockIdx.x * 32 + threadIdx.x;
    tile[threadIdx.y][threadIdx.x] = W[(size_t)k * D + n];
    __syncthreads();
    const int no = blockIdx.x * 32 + threadIdx.y;
    const int ko = blockIdx.y * 32 + threadIdx.x;
    Bt[(size_t)no * D + ko] = __float2half_rn(tile[threadIdx.x][threadIdx.y]);
}

// CSR row pointers from sorted rows
__global__ __launch_bounds__(256) void build_rowptr_kernel(const int* __restrict__ rows,
                                                           int* __restrict__ row_ptr) {
    const int e = blockIdx.x * blockDim.x + threadIdx.x;
    if (e >= N_EDGES) return;
    const int r = rows[e];
    const int r_prev = (e == 0) ? -1 : rows[e - 1];
    for (int k = r_prev + 1; k <= r; k++) row_ptr[k] = e;
    if (e == N_EDGES - 1) {
        for (int k = r + 1; k <= N_NODES; k++) row_ptr[k] = N_EDGES;
    }
}

// ---------------------------------------------------------------------------
// fp16 HMMA GEMM (measured 75.7us): h = A @ W, fp16 in/out, fp32 accum
// CTA tile 128x128, K chunk 64, 3-stage cp.async, SW128 smem,
// 8 warps (4m x 2n), warp tile 32x64, 2 CTAs/SM. FROZEN.
// ---------------------------------------------------------------------------
#define TILE_M 128
#define TILE_N 128
#define BKC 64
#define N_CHUNKS (D / BKC)     // 8
#define NSTAGE 3
#define A_OFF 0
#define B_OFF 16384
#define STAGE_BYTES 32768
#define GEMM_SMEM (NSTAGE * STAGE_BYTES)   // 96 KB -> 2 CTAs/SM

__device__ __forceinline__ void load_chunk(uint32_t sbase,
                                           const __half* __restrict__ Af,
                                           const __half* __restrict__ Bt,
                                           int mrow0, int nrow0, int k0, int tid) {
#pragma unroll
    for (int t = 0; t < 4; t++) {
        const int idx = t * 256 + tid;
        const int row = idx >> 3;
        const int c16 = idx & 7;
        const uint32_t soff = swz128((uint32_t)(row * 128 + c16 * 16));
        cp_async16(sbase + A_OFF + soff, Af + (size_t)(mrow0 + row) * D + k0 + c16 * 8);
        cp_async16(sbase + B_OFF + soff, Bt + (size_t)(nrow0 + row) * D + k0 + c16 * 8);
    }
    CP_COMMIT();
}

__global__ __launch_bounds__(256, 2) void gemm_mma_kernel(
    const __half* __restrict__ Af, const __half* __restrict__ Bt,
    __half* __restrict__ C) {
    extern __shared__ char smem[];
    const uint32_t sb = smem_to_u32(smem);
    const int tid = threadIdx.x;
    const int wid = tid >> 5;
    const int lane = tid & 31;

    const int mrow0 = blockIdx.y * TILE_M;
    const int nrow0 = blockIdx.x * TILE_N;

    const int m0 = (wid & 3) * 32;
    const int n0 = (wid >> 2) * 64;

    float acc[2][8][4];
#pragma unroll
    for (int mt = 0; mt < 2; mt++)
#pragma unroll
        for (int nt = 0; nt < 8; nt++)
#pragma unroll
            for (int q = 0; q < 4; q++) acc[mt][nt][q] = 0.f;

    load_chunk(sb + 0 * STAGE_BYTES, Af, Bt, mrow0, nrow0, 0 * BKC, tid);
    load_chunk(sb + 1 * STAGE_BYTES, Af, Bt, mrow0, nrow0, 1 * BKC, tid);
    load_chunk(sb + 2 * STAGE_BYTES, Af, Bt, mrow0, nrow0, 2 * BKC, tid);

    const int a_rowl = lane & 15;
    const int a_half = lane >> 4;
    const int b_g = lane >> 3;
    const int b_rowl = lane & 7;

    for (int c = 0; c < N_CHUNKS; c++) {
        if (c < N_CHUNKS - 2) { CP_WAIT(2); }
        else if (c == N_CHUNKS - 2) { CP_WAIT(1); }
        else { CP_WAIT(0); }
        __syncthreads();

        const uint32_t stage = sb + (uint32_t)(c % NSTAGE) * STAGE_BYTES;
        const uint32_t aS = stage + A_OFF, bS = stage + B_OFF;

#pragma unroll
        for (int ks = 0; ks < 4; ks++) {
            uint32_t a[2][4];
#pragma unroll
            for (int mt = 0; mt < 2; mt++) {
                const uint32_t aoff = swz128((uint32_t)((m0 + mt * 16 + a_rowl) * 128 + ks * 32 + a_half * 16));
                ldsm4(a[mt], aS + aoff);
            }
            uint32_t b[8][2];
#pragma unroll
            for (int jt = 0; jt < 4; jt++) {
                const int brow = n0 + (jt * 2 + (b_g >> 1)) * 8 + b_rowl;
                const int bkb = ks * 32 + (b_g & 1) * 16;
                const uint32_t boff = swz128((uint32_t)(brow * 128 + bkb));
                uint32_t t4[4];
                ldsm4(t4, bS + boff);
                b[jt * 2][0] = t4[0]; b[jt * 2][1] = t4[1];
                b[jt * 2 + 1][0] = t4[2]; b[jt * 2 + 1][1] = t4[3];
            }
#pragma unroll
            for (int mt = 0; mt < 2; mt++)
#pragma unroll
                for (int nt = 0; nt < 8; nt++)
                    mma16816h(acc[mt][nt], a[mt], b[nt]);
        }
        __syncthreads();
        if (c + NSTAGE < N_CHUNKS)
            load_chunk(stage, Af, Bt, mrow0, nrow0, (c + NSTAGE) * BKC, tid);
    }

    const int er = lane >> 2;
    const int ec = (lane & 3) * 2;
#pragma unroll
    for (int mt = 0; mt < 2; mt++) {
        const int r0 = mrow0 + m0 + mt * 16 + er;
#pragma unroll
        for (int nt = 0; nt < 8; nt++) {
            const int col = nrow0 + n0 + nt * 8 + ec;
            *reinterpret_cast<__half2*>(C + (size_t)r0 * D + col) =
                __floats2half2_rn(acc[mt][nt][0], acc[mt][nt][1]);
            *reinterpret_cast<__half2*>(C + (size_t)(r0 + 8) * D + col) =
                __floats2half2_rn(acc[mt][nt][2], acc[mt][nt][3]);
        }
    }
}

// ---------------------------------------------------------------------------
// SpMM + ReLU: 1 warp/row, lane = 16 dims, CSR row_ptr.
// Vectorized int4/float4 col+val loads (uniform -> broadcast), with
// alignment peel so e % 4 == 0 in the main loop.
// ---------------------------------------------------------------------------
__device__ __forceinline__ void fma8(float acc[8], const uint4& q, float v) {
    const __half2* hp = reinterpret_cast<const __half2*>(&q);
#pragma unroll
    for (int j = 0; j < 4; j++) {
        float2 f = __half22float2(hp[j]);
        acc[j * 2 + 0] = fmaf(v, f.x, acc[j * 2 + 0]);
        acc[j * 2 + 1] = fmaf(v, f.y, acc[j * 2 + 1]);
    }
}

__global__ __launch_bounds__(256) void spmm_relu_kernel(const int* __restrict__ row_ptr,
                                                        const int* __restrict__ cols,
                                                        const float* __restrict__ vals,
                                                        const __half* __restrict__ h,
                                                        float* __restrict__ out) {
    const int warp = threadIdx.x >> 5;
    const int lane = threadIdx.x & 31;
    const int r = blockIdx.x * (blockDim.x >> 5) + warp;
    if (r >= N_NODES) return;
    const int doff = lane * 16;

    const int start = __ldg(&row_ptr[r]);
    const int end = __ldg(&row_ptr[r + 1]);

    float acc[16];
#pragma unroll
    for (int j = 0; j < 16; j++) acc[j] = 0.f;

    int e = start;
    // peel to 16B alignment
    for (; e < end && (e & 3); e++) {
        const int c = __ldg(&cols[e]);
        const float v = __ldg(&vals[e]);
        const uint4* hp = reinterpret_cast<const uint4*>(h + (size_t)c * D + doff);
        const uint4 qa = hp[0];
        const uint4 qb = hp[1];
        fma8(acc, qa, v);
        fma8(acc + 8, qb, v);
    }
    // main: 4 edges per iter, vectorized cols/vals (broadcast loads)
    for (; e + 4 <= end; e += 4) {
        const int4 c4 = *reinterpret_cast<const int4*>(cols + e);
        const float4 v4 = *reinterpret_cast<const float4*>(vals + e);
        const uint4* h0 = reinterpret_cast<const uint4*>(h + (size_t)c4.x * D + doff);
        const uint4* h1 = reinterpret_cast<const uint4*>(h + (size_t)c4.y * D + doff);
        const uint4* h2 = reinterpret_cast<const uint4*>(h + (size_t)c4.z * D + doff);
        const uint4* h3 = reinterpret_cast<const uint4*>(h + (size_t)c4.w * D + doff);
        const uint4 qa0 = h0[0], qb0 = h0[1];
        const uint4 qa1 = h1[0], qb1 = h1[1];
        const uint4 qa2 = h2[0], qb2 = h2[1];
        const uint4 qa3 = h3[0], qb3 = h3[1];
        fma8(acc, qa0, v4.x); fma8(acc + 8, qb0, v4.x);
        fma8(acc, qa1, v4.y); fma8(acc + 8, qb1, v4.y);
        fma8(acc, qa2, v4.z); fma8(acc + 8, qb2, v4.z);
        fma8(acc, qa3, v4.w); fma8(acc + 8, qb3, v4.w);
    }
    // tail
    for (; e < end; e++) {
        const int c = __ldg(&cols[e]);
        const float v = __ldg(&vals[e]);
        const uint4* hp = reinterpret_cast<const uint4*>(h + (size_t)c * D + doff);
        const uint4 qa = hp[0];
        const uint4 qb = hp[1];
        fma8(acc, qa, v);
        fma8(acc + 8, qb, v);
    }

    float4* op = reinterpret_cast<float4*>(out + (size_t)r * D + doff);
#pragma unroll
    for (int j = 0; j < 4; j++) {
        op[j] = make_float4(fmaxf(acc[j * 4 + 0], 0.f), fmaxf(acc[j * 4 + 1], 0.f),
                            fmaxf(acc[j * 4 + 2], 0.f), fmaxf(acc[j * 4 + 3], 0.f));
    }
}

// ---------------------------------------------------------------------------
// kernel_launch
// ---------------------------------------------------------------------------
extern "C" void kernel_launch(void* const* d_in, const int* in_sizes, int n_in,
                              void* d_out, int out_size) {
    const int* adj_rows = (const int*)d_in[0];
    const int* adj_cols = (const int*)d_in[1];
    const float* adj_vals = (const float*)d_in[2];
    const float* u_f = (const float*)d_in[3];
    const float* weight = (const float*)d_in[4];
    float* out = (float*)d_out;

    __half* h;  cudaGetSymbolAddress((void**)&h, g_h);
    __half* Af; cudaGetSymbolAddress((void**)&Af, g_Af);
    __half* Bt; cudaGetSymbolAddress((void**)&Bt, g_Btf);
    int* rp;    cudaGetSymbolAddress((void**)&rp, g_rowptr);

    cudaFuncSetAttribute(gemm_mma_kernel, cudaFuncAttributeMaxDynamicSharedMemorySize, GEMM_SMEM);

    const size_t total4 = (size_t)M_PAD * D / 4;
    convertA_kernel<<<(unsigned)((total4 + 255) / 256), 256>>>(u_f, Af);
    convertW_kernel<<<dim3(D / 32, D / 32), dim3(32, 32)>>>(weight, Bt);
    build_rowptr_kernel<<<(N_EDGES + 255) / 256, 256>>>(adj_rows, rp);

    dim3 ggrid(D / TILE_N, M_PAD / TILE_M);   // (4, 391)
    gemm_mma_kernel<<<ggrid, 256, GEMM_SMEM>>>(Af, Bt, h);

    const int warps_per_block = 8;
    const int nblocks = (N_NODES + warps_per_block - 1) / warps_per_block;
    spmm_relu_kernel<<<nblocks, 256>>>(rp, adj_cols, adj_vals, h, out);
}

// round 15
// speedup vs baseline: 1.4466x; 1.4466x over previous
#include <cuda_runtime.h>
#include <cuda_fp16.h>
#include <cstdint>

#define N_NODES 50000
#define N_EDGES 800000
#define D 512
#define M_PAD 50048            // 391 * 128

// ---------------------------------------------------------------------------
// Device scratch
// ---------------------------------------------------------------------------
__device__ __half g_h[(size_t)M_PAD * D];                // GEMM output fp16 (51.2 MB)
__device__ __half g_Af[(size_t)M_PAD * D];               // A in fp16 (51.2 MB)
__device__ __half g_Btf[(size_t)D * D];                  // weight^T fp16 [n][k]
__device__ int g_rowptr[N_NODES + 1];

// ---------------------------------------------------------------------------
// helpers
// ---------------------------------------------------------------------------
__device__ __forceinline__ uint32_t smem_to_u32(const void* p) {
    uint32_t a;
    asm("{ .reg .u64 t; cvta.to.shared.u64 t, %1; cvt.u32.u64 %0, t; }" : "=r"(a) : "l"(p));
    return a;
}
__device__ __forceinline__ uint32_t swz128(uint32_t o) { return o ^ ((o >> 3) & 0x70); }

__device__ __forceinline__ void cp_async16(uint32_t saddr, const void* gptr) {
    asm volatile("cp.async.cg.shared.global [%0], [%1], 16;" :: "r"(saddr), "l"(gptr));
}
#define CP_COMMIT() asm volatile("cp.async.commit_group;" ::: "memory")
#define CP_WAIT(n) asm volatile("cp.async.wait_group %0;" :: "n"(n) : "memory")

__device__ __forceinline__ void ldsm4(uint32_t r[4], uint32_t addr) {
    asm volatile("ldmatrix.sync.aligned.m8n8.x4.shared.b16 {%0,%1,%2,%3}, [%4];"
                 : "=r"(r[0]), "=r"(r[1]), "=r"(r[2]), "=r"(r[3]) : "r"(addr));
}
__device__ __forceinline__ void mma16816h(float c[4], const uint32_t a[4], const uint32_t b[2]) {
    asm volatile("mma.sync.aligned.m16n8k16.row.col.f32.f16.f16.f32 "
                 "{%0,%1,%2,%3}, {%4,%5,%6,%7}, {%8,%9}, {%0,%1,%2,%3};"
                 : "+f"(c[0]), "+f"(c[1]), "+f"(c[2]), "+f"(c[3])
                 : "r"(a[0]), "r"(a[1]), "r"(a[2]), "r"(a[3]), "r"(b[0]), "r"(b[1]));
}

// ---------------------------------------------------------------------------
// Convert kernels (fp32 -> fp16)
// ---------------------------------------------------------------------------
__global__ __launch_bounds__(256) void convertA_kernel(const float* __restrict__ A,
                                                       __half* __restrict__ Af) {
    const size_t i4 = (size_t)blockIdx.x * blockDim.x + threadIdx.x;
    const size_t total4 = (size_t)M_PAD * D / 4;
    if (i4 >= total4) return;
    const size_t elem = i4 * 4;
    const size_t row = elem >> 9;
    float4 v = make_float4(0.f, 0.f, 0.f, 0.f);
    if (row < N_NODES) v = *reinterpret_cast<const float4*>(A + elem);
    __half2* p = reinterpret_cast<__half2*>(Af + elem);
    p[0] = __floats2half2_rn(v.x, v.y);
    p[1] = __floats2half2_rn(v.z, v.w);
}

// weight [k][n] row-major -> Bt[n][k] fp16
__global__ void convertW_kernel(const float* __restrict__ W, __half* __restrict__ Bt) {
    __shared__ float tile[32][33];
    const int k = blockIdx.y * 32 + threadIdx.y;
    const int n = blockIdx.x * 32 + threadIdx.x;
    tile[threadIdx.y][threadIdx.x] = W[(size_t)k * D + n];
    __syncthreads();
    const int no = blockIdx.x * 32 + threadIdx.y;
    const int ko = blockIdx.y * 32 + threadIdx.x;
    Bt[(size_t)no * D + ko] = __float2half_rn(tile[threadIdx.x][threadIdx.y]);
}

// CSR row pointers from sorted rows
__global__ __launch_bounds__(256) void build_rowptr_kernel(const int* __restrict__ rows,
                                                           int* __restrict__ row_ptr) {
    const int e = blockIdx.x * blockDim.x + threadIdx.x;
    if (e >= N_EDGES) return;
    const int r = rows[e];
    const int r_prev = (e == 0) ? -1 : rows[e - 1];
    for (int k = r_prev + 1; k <= r; k++) row_ptr[k] = e;
    if (e == N_EDGES - 1) {
        for (int k = r + 1; k <= N_NODES; k++) row_ptr[k] = N_EDGES;
    }
}

// ---------------------------------------------------------------------------
// fp16 HMMA GEMM (measured 75.7us @ R9 clocks): h = A @ W, fp16 in/out,
// fp32 accum. CTA tile 128x128, K chunk 64, 3-stage cp.async, SW128 smem,
// 8 warps (4m x 2n), warp tile 32x64, 2 CTAs/SM. FROZEN.
// ---------------------------------------------------------------------------
#define TILE_M 128
#define TILE_N 128
#define BKC 64
#define N_CHUNKS (D / BKC)     // 8
#define NSTAGE 3
#define A_OFF 0
#define B_OFF 16384
#define STAGE_BYTES 32768
#define GEMM_SMEM (NSTAGE * STAGE_BYTES)   // 96 KB -> 2 CTAs/SM

__device__ __forceinline__ void load_chunk(uint32_t sbase,
                                           const __half* __restrict__ Af,
                                           const __half* __restrict__ Bt,
                                           int mrow0, int nrow0, int k0, int tid) {
#pragma unroll
    for (int t = 0; t < 4; t++) {
        const int idx = t * 256 + tid;
        const int row = idx >> 3;
        const int c16 = idx & 7;
        const uint32_t soff = swz128((uint32_t)(row * 128 + c16 * 16));
        cp_async16(sbase + A_OFF + soff, Af + (size_t)(mrow0 + row) * D + k0 + c16 * 8);
        cp_async16(sbase + B_OFF + soff, Bt + (size_t)(nrow0 + row) * D + k0 + c16 * 8);
    }
    CP_COMMIT();
}

__global__ __launch_bounds__(256, 2) void gemm_mma_kernel(
    const __half* __restrict__ Af, const __half* __restrict__ Bt,
    __half* __restrict__ C) {
    extern __shared__ char smem[];
    const uint32_t sb = smem_to_u32(smem);
    const int tid = threadIdx.x;
    const int wid = tid >> 5;
    const int lane = tid & 31;

    const int mrow0 = blockIdx.y * TILE_M;
    const int nrow0 = blockIdx.x * TILE_N;

    const int m0 = (wid & 3) * 32;
    const int n0 = (wid >> 2) * 64;

    float acc[2][8][4];
#pragma unroll
    for (int mt = 0; mt < 2; mt++)
#pragma unroll
        for (int nt = 0; nt < 8; nt++)
#pragma unroll
            for (int q = 0; q < 4; q++) acc[mt][nt][q] = 0.f;

    load_chunk(sb + 0 * STAGE_BYTES, Af, Bt, mrow0, nrow0, 0 * BKC, tid);
    load_chunk(sb + 1 * STAGE_BYTES, Af, Bt, mrow0, nrow0, 1 * BKC, tid);
    load_chunk(sb + 2 * STAGE_BYTES, Af, Bt, mrow0, nrow0, 2 * BKC, tid);

    const int a_rowl = lane & 15;
    const int a_half = lane >> 4;
    const int b_g = lane >> 3;
    const int b_rowl = lane & 7;

    for (int c = 0; c < N_CHUNKS; c++) {
        if (c < N_CHUNKS - 2) { CP_WAIT(2); }
        else if (c == N_CHUNKS - 2) { CP_WAIT(1); }
        else { CP_WAIT(0); }
        __syncthreads();

        const uint32_t stage = sb + (uint32_t)(c % NSTAGE) * STAGE_BYTES;
        const uint32_t aS = stage + A_OFF, bS = stage + B_OFF;

#pragma unroll
        for (int ks = 0; ks < 4; ks++) {
            uint32_t a[2][4];
#pragma unroll
            for (int mt = 0; mt < 2; mt++) {
                const uint32_t aoff = swz128((uint32_t)((m0 + mt * 16 + a_rowl) * 128 + ks * 32 + a_half * 16));
                ldsm4(a[mt], aS + aoff);
            }
            uint32_t b[8][2];
#pragma unroll
            for (int jt = 0; jt < 4; jt++) {
                const int brow = n0 + (jt * 2 + (b_g >> 1)) * 8 + b_rowl;
                const int bkb = ks * 32 + (b_g & 1) * 16;
                const uint32_t boff = swz128((uint32_t)(brow * 128 + bkb));
                uint32_t t4[4];
                ldsm4(t4, bS + boff);
                b[jt * 2][0] = t4[0]; b[jt * 2][1] = t4[1];
                b[jt * 2 + 1][0] = t4[2]; b[jt * 2 + 1][1] = t4[3];
            }
#pragma unroll
            for (int mt = 0; mt < 2; mt++)
#pragma unroll
                for (int nt = 0; nt < 8; nt++)
                    mma16816h(acc[mt][nt], a[mt], b[nt]);
        }
        __syncthreads();
        if (c + NSTAGE < N_CHUNKS)
            load_chunk(stage, Af, Bt, mrow0, nrow0, (c + NSTAGE) * BKC, tid);
    }

    const int er = lane >> 2;
    const int ec = (lane & 3) * 2;
#pragma unroll
    for (int mt = 0; mt < 2; mt++) {
        const int r0 = mrow0 + m0 + mt * 16 + er;
#pragma unroll
        for (int nt = 0; nt < 8; nt++) {
            const int col = nrow0 + n0 + nt * 8 + ec;
            *reinterpret_cast<__half2*>(C + (size_t)r0 * D + col) =
                __floats2half2_rn(acc[mt][nt][0], acc[mt][nt][1]);
            *reinterpret_cast<__half2*>(C + (size_t)(r0 + 8) * D + col) =
                __floats2half2_rn(acc[mt][nt][2], acc[mt][nt][3]);
        }
    }
}

// ---------------------------------------------------------------------------
// SpMM + ReLU: 1 warp/row, lane = 16 dims, CSR row_ptr.
// Vectorized int4/float4 col+val loads (uniform -> broadcast), with
// alignment peel so e % 4 == 0 in the main loop.
// ---------------------------------------------------------------------------
__device__ __forceinline__ void fma8(float acc[8], const uint4& q, float v) {
    const __half2* hp = reinterpret_cast<const __half2*>(&q);
#pragma unroll
    for (int j = 0; j < 4; j++) {
        float2 f = __half22float2(hp[j]);
        acc[j * 2 + 0] = fmaf(v, f.x, acc[j * 2 + 0]);
        acc[j * 2 + 1] = fmaf(v, f.y, acc[j * 2 + 1]);
    }
}

__global__ __launch_bounds__(256) void spmm_relu_kernel(const int* __restrict__ row_ptr,
                                                        const int* __restrict__ cols,
                                                        const float* __restrict__ vals,
                                                        const __half* __restrict__ h,
                                                        float* __restrict__ out) {
    const int warp = threadIdx.x >> 5;
    const int lane = threadIdx.x & 31;
    const int r = blockIdx.x * (blockDim.x >> 5) + warp;
    if (r >= N_NODES) return;
    const int doff = lane * 16;

    const int start = __ldg(&row_ptr[r]);
    const int end = __ldg(&row_ptr[r + 1]);

    float acc[16];
#pragma unroll
    for (int j = 0; j < 16; j++) acc[j] = 0.f;

    int e = start;
    // peel to 16B alignment
    for (; e < end && (e & 3); e++) {
        const int c = __ldg(&cols[e]);
        const float v = __ldg(&vals[e]);
        const uint4* hp = reinterpret_cast<const uint4*>(h + (size_t)c * D + doff);
        const uint4 qa = hp[0];
        const uint4 qb = hp[1];
        fma8(acc, qa, v);
        fma8(acc + 8, qb, v);
    }
    // main: 4 edges per iter, vectorized cols/vals (broadcast loads)
    for (; e + 4 <= end; e += 4) {
        const int4 c4 = *reinterpret_cast<const int4*>(cols + e);
        const float4 v4 = *reinterpret_cast<const float4*>(vals + e);
        const uint4* h0 = reinterpret_cast<const uint4*>(h + (size_t)c4.x * D + doff);
        const uint4* h1 = reinterpret_cast<const uint4*>(h + (size_t)c4.y * D + doff);
        const uint4* h2 = reinterpret_cast<const uint4*>(h + (size_t)c4.z * D + doff);
        const uint4* h3 = reinterpret_cast<const uint4*>(h + (size_t)c4.w * D + doff);
        const uint4 qa0 = h0[0], qb0 = h0[1];
        const uint4 qa1 = h1[0], qb1 = h1[1];
        const uint4 qa2 = h2[0], qb2 = h2[1];
        const uint4 qa3 = h3[0], qb3 = h3[1];
        fma8(acc, qa0, v4.x); fma8(acc + 8, qb0, v4.x);
        fma8(acc, qa1, v4.y); fma8(acc + 8, qb1, v4.y);
        fma8(acc, qa2, v4.z); fma8(acc + 8, qb2, v4.z);
        fma8(acc, qa3, v4.w); fma8(acc + 8, qb3, v4.w);
    }
    // tail
    for (; e < end; e++) {
        const int c = __ldg(&cols[e]);
        const float v = __ldg(&vals[e]);
        const uint4* hp = reinterpret_cast<const uint4*>(h + (size_t)c * D + doff);
        const uint4 qa = hp[0];
        const uint4 qb = hp[1];
        fma8(acc, qa, v);
        fma8(acc + 8, qb, v);
    }

    float4* op = reinterpret_cast<float4*>(out + (size_t)r * D + doff);
#pragma unroll
    for (int j = 0; j < 4; j++) {
        op[j] = make_float4(fmaxf(acc[j * 4 + 0], 0.f), fmaxf(acc[j * 4 + 1], 0.f),
                            fmaxf(acc[j * 4 + 2], 0.f), fmaxf(acc[j * 4 + 3], 0.f));
    }
}

// ---------------------------------------------------------------------------
// kernel_launch
// ---------------------------------------------------------------------------
extern "C" void kernel_launch(void* const* d_in, const int* in_sizes, int n_in,
                              void* d_out, int out_size) {
    const int* adj_rows = (const int*)d_in[0];
    const int* adj_cols = (const int*)d_in[1];
    const float* adj_vals = (const float*)d_in[2];
    const float* u_f = (const float*)d_in[3];
    const float* weight = (const float*)d_in[4];
    float* out = (float*)d_out;

    __half* h;  cudaGetSymbolAddress((void**)&h, g_h);
    __half* Af; cudaGetSymbolAddress((void**)&Af, g_Af);
    __half* Bt; cudaGetSymbolAddress((void**)&Bt, g_Btf);
    int* rp;    cudaGetSymbolAddress((void**)&rp, g_rowptr);

    cudaFuncSetAttribute(gemm_mma_kernel, cudaFuncAttributeMaxDynamicSharedMemorySize, GEMM_SMEM);

    const size_t total4 = (size_t)M_PAD * D / 4;
    convertA_kernel<<<(unsigned)((total4 + 255) / 256), 256>>>(u_f, Af);
    convertW_kernel<<<dim3(D / 32, D / 32), dim3(32, 32)>>>(weight, Bt);
    build_rowptr_kernel<<<(N_EDGES + 255) / 256, 256>>>(adj_rows, rp);

    dim3 ggrid(D / TILE_N, M_PAD / TILE_M);   // (4, 391)
    gemm_mma_kernel<<<ggrid, 256, GEMM_SMEM>>>(Af, Bt, h);

    const int warps_per_block = 8;
    const int nblocks = (N_NODES + warps_per_block - 1) / warps_per_block;
    spmm_relu_kernel<<<nblocks, 256>>>(rp, adj_cols, adj_vals, h, out);
}